// round 14
// baseline (speedup 1.0000x reference)
#include <cuda_runtime.h>
#include <cuda_fp16.h>
#include <cstdint>

#define T_TOK 2048
#define DIM   768
#define HID   3072
#define NEXP  8

// ---------------- scratch (device globals) ----------------------------------
__device__ int   g_cnt[NEXP];                        // zero-init; re-zeroed by combine
__device__ int   g_plist[NEXP * T_TOK];
__device__ float g_pw[2 * T_TOK];
__device__ float g_moe2[(size_t)2 * 2 * T_TOK * DIM];  // [khalf][pair][D]
__device__ float g_sh2 [(size_t)2 * T_TOK * DIM];      // [khalf][tok][D]

__device__ __align__(16) __half g_x  [(size_t)T_TOK * DIM];
__device__ __align__(16) __half g_hs [(size_t)T_TOK * HID];
__device__ __align__(16) __half g_h  [(size_t)2 * T_TOK * HID];
__device__ __align__(16) __half g_w1h [(size_t)NEXP * DIM * HID];  // native [K,N]
__device__ __align__(16) __half g_ws1h[(size_t)DIM * HID];
__device__ __align__(16) __half g_w2h [(size_t)NEXP * HID * DIM];
__device__ __align__(16) __half g_ws2h[(size_t)HID * DIM];

// ---------------- helpers ----------------------------------------------------
__device__ __forceinline__ uint32_t smem_u32(const void* p) {
    uint32_t a;
    asm("{ .reg .u64 t; cvta.to.shared.u64 t, %1; cvt.u32.u64 %0, t; }"
        : "=r"(a) : "l"(p));
    return a;
}
#define CP16(saddr, gptr) \
    asm volatile("cp.async.cg.shared.global [%0], [%1], 16;" \
                 :: "r"(saddr), "l"(gptr) : "memory")
#define CP_COMMIT() asm volatile("cp.async.commit_group;" ::: "memory")
template <int N>
__device__ __forceinline__ void cp_wait() {
    asm volatile("cp.async.wait_group %0;" :: "n"(N) : "memory");
}
#define LDM_X4(r, addr) \
    asm volatile("ldmatrix.sync.aligned.m8n8.x4.shared.b16 {%0,%1,%2,%3}, [%4];" \
                 : "=r"((r)[0]), "=r"((r)[1]), "=r"((r)[2]), "=r"((r)[3]) \
                 : "r"(addr))
#define LDM_X4_T(r, addr) \
    asm volatile("ldmatrix.sync.aligned.m8n8.x4.trans.shared.b16 {%0,%1,%2,%3}, [%4];" \
                 : "=r"((r)[0]), "=r"((r)[1]), "=r"((r)[2]), "=r"((r)[3]) \
                 : "r"(addr))
__device__ __forceinline__ void mma16816(float* d, const uint32_t* a,
                                         uint32_t b0, uint32_t b1) {
    asm volatile(
        "mma.sync.aligned.m16n8k16.row.col.f32.f16.f16.f32 "
        "{%0,%1,%2,%3}, {%4,%5,%6,%7}, {%8,%9}, {%0,%1,%2,%3};"
        : "+f"(d[0]), "+f"(d[1]), "+f"(d[2]), "+f"(d[3])
        : "r"(a[0]), "r"(a[1]), "r"(a[2]), "r"(a[3]), "r"(b0), "r"(b1));
}

// ---------------- router: one warp per token --------------------------------
__global__ void router_kernel(const float* __restrict__ x,
                              const float* __restrict__ noise,
                              const float* __restrict__ Wr,
                              const float* __restrict__ br) {
    int warp = (blockIdx.x * blockDim.x + threadIdx.x) >> 5;
    int lane = threadIdx.x & 31;
    if (warp >= T_TOK) return;
    const float* xr = x + warp * DIM;
    float acc[8] = {0.f, 0.f, 0.f, 0.f, 0.f, 0.f, 0.f, 0.f};
    for (int j = lane; j < DIM; j += 32) {
        float xv = xr[j];
        const float4* w4 = reinterpret_cast<const float4*>(Wr + j * NEXP);
        float4 wa = w4[0], wb = w4[1];
        acc[0] += xv * wa.x; acc[1] += xv * wa.y;
        acc[2] += xv * wa.z; acc[3] += xv * wa.w;
        acc[4] += xv * wb.x; acc[5] += xv * wb.y;
        acc[6] += xv * wb.z; acc[7] += xv * wb.w;
    }
#pragma unroll
    for (int off = 16; off; off >>= 1)
#pragma unroll
        for (int e = 0; e < 8; e++)
            acc[e] += __shfl_xor_sync(0xffffffffu, acc[e], off);
    if (lane == 0) {
        float lg[8];
#pragma unroll
        for (int e = 0; e < 8; e++)
            lg[e] = acc[e] + br[e] + 0.1f * noise[warp * NEXP + e];
        int i0 = 0;
#pragma unroll
        for (int e = 1; e < 8; e++) if (lg[e] > lg[i0]) i0 = e;
        int i1 = (i0 == 0) ? 1 : 0;
#pragma unroll
        for (int e = 0; e < 8; e++) if (e != i0 && lg[e] > lg[i1]) i1 = e;
        float e1 = expf(lg[i1] - lg[i0]);
        float w0 = 1.0f / (1.0f + e1);
        g_pw[2 * warp]     = w0;
        g_pw[2 * warp + 1] = e1 * w0;
        int p0 = atomicAdd(&g_cnt[i0], 1);
        g_plist[i0 * T_TOK + p0] = 2 * warp;
        int p1 = atomicAdd(&g_cnt[i1], 1);
        g_plist[i1 * T_TOK + p1] = 2 * warp + 1;
    }
}

// ---------------- prep: x -> fp16 -------------------------------------------
__global__ void prep_x_kernel(const float* __restrict__ x) {
    int i = blockIdx.x * blockDim.x + threadIdx.x;
    const int n4 = T_TOK * DIM / 4;
    if (i >= n4) return;
    float4 v = reinterpret_cast<const float4*>(x)[i];
    __half2 h0 = __floats2half2_rn(v.x, v.y);
    __half2 h1 = __floats2half2_rn(v.z, v.w);
    uint2 pk;
    pk.x = *reinterpret_cast<uint32_t*>(&h0);
    pk.y = *reinterpret_cast<uint32_t*>(&h1);
    reinterpret_cast<uint2*>(g_x)[i] = pk;
}

// ---------------- conv: one layer's weights (expert + shared) ----------------
__global__ void conv_w_kernel(const float4* __restrict__ srcE,
                              uint2* __restrict__ dstE, int nE,
                              const float4* __restrict__ srcS,
                              uint2* __restrict__ dstS, int nS) {
    int i = blockIdx.x * blockDim.x + threadIdx.x;
    const float4* src;
    uint2* dst;
    int j;
    if (i < nE)           { src = srcE; dst = dstE; j = i; }
    else if (i < nE + nS) { src = srcS; dst = dstS; j = i - nE; }
    else return;
    float4 v = src[j];
    __half2 h0 = __floats2half2_rn(v.x, v.y);
    __half2 h1 = __floats2half2_rn(v.z, v.w);
    uint2 pk;
    pk.x = *reinterpret_cast<uint32_t*>(&h0);
    pk.y = *reinterpret_cast<uint32_t*>(&h1);
    dst[j] = pk;
}

// ---------------- HMMA GEMM, 3-stage cp.async ring, occ=2 --------------------
// block 128x128, 8 warps 4(M)x2(N), warp tile 32x64, K-chunk 32.
// A smem: [row][k] 80B pitch; B smem: [k][n] 272B pitch (native [K,N] weights,
// ldmatrix.trans). One __syncthreads per K-chunk.
// grid.z: z<8 => expert z (gathered rows); z==8 => shared expert (dense).
// LAYER==2 uses split-K=2: grid.x = 2*bn_tiles, x&1 = k-half; halves write
// disjoint buffers (bias applied by half 0 only). LAYER 2 is linear, so the
// halves sum exactly in combine.
template <int LAYER>
__global__ __launch_bounds__(256, 2)
void mma_gemm(const float* __restrict__ bias_moe,
              const float* __restrict__ bias_sh) {
    constexpr int K  = (LAYER == 1) ? DIM : HID;
    constexpr int N  = (LAYER == 1) ? HID : DIM;
    constexpr int KS = (LAYER == 1) ? 1 : 2;     // split-K factor
    constexpr int KL = K / KS;                   // local K per CTA
    constexpr int S  = KL / 32;
    constexpr int BUFA = 128 * 80;    // 10240
    constexpr int BUFB = 32 * 272;    // 8704

    const int bn = (LAYER == 1) ? blockIdx.x : (blockIdx.x >> 1);
    const int kh = (LAYER == 1) ? 0 : (blockIdx.x & 1);
    const int bm = blockIdx.y, e = blockIdx.z;
    const bool sh = (e == NEXP);
    const int M = sh ? T_TOK : g_cnt[e];
    if (bm * 128 >= M) return;

    const __half* Bg;
    const float* bp;
    if (LAYER == 1) {
        Bg = sh ? g_ws1h : g_w1h + (size_t)e * DIM * HID;
        bp = (sh ? bias_sh : bias_moe + e * HID) + bn * 128;
    } else {
        Bg = sh ? g_ws2h : g_w2h + (size_t)e * HID * DIM;
        bp = (sh ? bias_sh : bias_moe + e * DIM) + bn * 128;
    }
    Bg += bn * 128;
    const float bsc = (kh == 0) ? 1.0f : 0.0f;   // bias only in half 0

    extern __shared__ __align__(16) char dsm[];
    char* sm_a = dsm;                 // 3 x BUFA
    char* sm_b = dsm + 3 * BUFA;      // 3 x BUFB
    __shared__ int plist_s[128];

    const int tid = threadIdx.x;
    const int lid = tid & 31, wid = tid >> 5;
    const int wm = wid >> 1, wn = wid & 1;

    if (!sh) {
        if (tid < 128) {
            int r = bm * 128 + tid;
            plist_s[tid] = (r < M) ? g_plist[e * T_TOK + tid + bm * 128] : -1;
        }
        __syncthreads();
    }

    // ---- A cp.async: 2 threads per row, 32B each ----
    const int lrow = tid >> 1;
    const int c4   = (tid & 1) * 2;
    const __half* arow;
    if (sh) {
        arow = ((LAYER == 1) ? g_x : g_hs) + (size_t)(bm * 128 + lrow) * K;
    } else {
        int p  = plist_s[lrow];
        int rr = (p >= 0) ? ((LAYER == 1) ? (p >> 1) : p) : 0;
        arow = ((LAYER == 1) ? g_x : g_h) + (size_t)rr * K;
    }
    arow += kh * KL + c4 * 8;
    const uint32_t sa0 = smem_u32(sm_a) + lrow * 80 + c4 * 16;

    // ---- B cp.async: [k][n] rows, 272B pitch ----
    const int brow_ = tid >> 3;
    const int bseg  = (tid & 7) * 2;
    const __half* bgp = Bg + (size_t)(brow_ + kh * KL) * N + bseg * 8;
    const uint32_t sb0 = smem_u32(sm_b) + brow_ * 272 + bseg * 16;

    // ---- ldmatrix bases ----
    const uint32_t aBase = smem_u32(sm_a)
        + (wm * 32 + ((lid >> 3) & 1) * 8 + (lid & 7)) * 80
        + (((lid >> 4) & 1) * 8) * 2;
    const int bmx = lid >> 3, brr = lid & 7;
    const uint32_t bBase = smem_u32(sm_b)
        + (brr + (bmx & 1) * 8) * 272
        + (wn * 64 + (bmx >> 1) * 8) * 2;

    float acc[2][8][4];
#pragma unroll
    for (int i = 0; i < 2; i++)
#pragma unroll
        for (int j = 0; j < 8; j++)
#pragma unroll
            for (int k = 0; k < 4; k++) acc[i][j][k] = 0.0f;

    auto load_stage = [&](int st) {
        const __half* ga = arow + st * 32;
        const __half* gb = bgp + (size_t)st * 32 * N;
        const uint32_t da = sa0 + (st % 3) * BUFA;
        const uint32_t db = sb0 + (st % 3) * BUFB;
        CP16(da,      ga);
        CP16(da + 16, ga + 8);
        CP16(db,      gb);
        CP16(db + 16, gb + 8);
    };

    load_stage(0); CP_COMMIT();
    load_stage(1); CP_COMMIT();

    for (int s = 0; s < S; ++s) {
        cp_wait<1>();
        __syncthreads();
        if (s + 2 < S) load_stage(s + 2);
        CP_COMMIT();

        const uint32_t ab = (s % 3) * BUFA;
        const uint32_t bb = (s % 3) * BUFB;
#pragma unroll
        for (int kk = 0; kk < 32; kk += 16) {
            uint32_t af[2][4], bt[4][4];
#pragma unroll
            for (int mi = 0; mi < 2; mi++)
                LDM_X4(af[mi], aBase + ab + mi * 16 * 80 + kk * 2);
#pragma unroll
            for (int g = 0; g < 4; g++)
                LDM_X4_T(bt[g], bBase + bb + kk * 272 + g * 32);
#pragma unroll
            for (int mi = 0; mi < 2; mi++)
#pragma unroll
                for (int g = 0; g < 4; g++) {
                    mma16816(acc[mi][2 * g],     af[mi], bt[g][0], bt[g][1]);
                    mma16816(acc[mi][2 * g + 1], af[mi], bt[g][2], bt[g][3]);
                }
        }
    }

    // ---- epilogue ----
    const int lr = lid >> 2;
    const int lc = (lid & 3) * 2;
#pragma unroll
    for (int mi = 0; mi < 2; mi++) {
#pragma unroll
        for (int h = 0; h < 2; h++) {
            int rl = wm * 32 + mi * 16 + h * 8 + lr;
            int r  = bm * 128 + rl;
            int p = 0;
            float gw = 0.f;
            if (!sh) {
                p = plist_s[rl];
                if (p < 0) continue;
                gw = g_pw[p];
            }
            if (LAYER == 1) {
                __half* dh = sh ? (g_hs + (size_t)r * HID)
                                : (g_h  + (size_t)p * HID);
#pragma unroll
                for (int nj = 0; nj < 8; nj++) {
                    int cl = wn * 64 + nj * 8 + lc;
                    float v0 = acc[mi][nj][2 * h]     + bp[cl];
                    float v1 = acc[mi][nj][2 * h + 1] + bp[cl + 1];
                    v0 = (v0 > 0.f) ? v0 : 0.01f * v0;
                    v1 = (v1 > 0.f) ? v1 : 0.01f * v1;
                    *reinterpret_cast<__half2*>(dh + bn * 128 + cl) =
                        __floats2half2_rn(v0, v1);
                }
            } else if (sh) {
                float* d = g_sh2 + ((size_t)kh * T_TOK + r) * DIM;
#pragma unroll
                for (int nj = 0; nj < 8; nj++) {
                    int cl = wn * 64 + nj * 8 + lc;
                    float2 v;
                    v.x = acc[mi][nj][2 * h]     + bsc * bp[cl];
                    v.y = acc[mi][nj][2 * h + 1] + bsc * bp[cl + 1];
                    *reinterpret_cast<float2*>(d + bn * 128 + cl) = v;
                }
            } else {
                float* d = g_moe2 + ((size_t)kh * 2 * T_TOK + p) * DIM;
#pragma unroll
                for (int nj = 0; nj < 8; nj++) {
                    int cl = wn * 64 + nj * 8 + lc;
                    float2 v;
                    v.x = gw * (acc[mi][nj][2 * h]     + bsc * bp[cl]);
                    v.y = gw * (acc[mi][nj][2 * h + 1] + bsc * bp[cl + 1]);
                    *reinterpret_cast<float2*>(d + bn * 128 + cl) = v;
                }
            }
        }
    }
}

// ---------------- final mix (float4) + counter reset --------------------------
__global__ void combine_kernel(const float* __restrict__ alpha,
                               const float* __restrict__ beta,
                               float4* __restrict__ out) {
    // reset expert counters for the next graph replay (all GEMMs already done)
    if (blockIdx.x == 0 && threadIdx.x < NEXP) g_cnt[threadIdx.x] = 0;

    float a = *alpha, b = *beta;
    float m  = fmaxf(a, b);
    float ea = expf(a - m), eb = expf(b - m);
    float inv = 1.0f / (ea + eb);
    float w0 = ea * inv, w1 = eb * inv;
    const int D4 = DIM / 4;
    const int n4 = T_TOK * D4;
    int i = blockIdx.x * blockDim.x + threadIdx.x;
    if (i >= n4) return;
    int t = i / D4, j = i - t * D4;
    const float4* m4 = reinterpret_cast<const float4*>(g_moe2);
    const float4* s4 = reinterpret_cast<const float4*>(g_sh2);
    const size_t HM = (size_t)2 * T_TOK * D4;     // moe half stride (in float4)
    const size_t HS = (size_t)T_TOK * D4;         // shared half stride
    float4 m00 = m4[(size_t)(2 * t) * D4 + j];
    float4 m01 = m4[(size_t)(2 * t + 1) * D4 + j];
    float4 m10 = m4[HM + (size_t)(2 * t) * D4 + j];
    float4 m11 = m4[HM + (size_t)(2 * t + 1) * D4 + j];
    float4 s0  = s4[i];
    float4 s1  = s4[HS + i];
    float4 o;
    o.x = w0 * (s0.x + s1.x) + w1 * (m00.x + m01.x + m10.x + m11.x);
    o.y = w0 * (s0.y + s1.y) + w1 * (m00.y + m01.y + m10.y + m11.y);
    o.z = w0 * (s0.z + s1.z) + w1 * (m00.z + m01.z + m10.z + m11.z);
    o.w = w0 * (s0.w + s1.w) + w1 * (m00.w + m01.w + m10.w + m11.w);
    out[i] = o;
}

// ---------------- launch ----------------------------------------------------
extern "C" void kernel_launch(void* const* d_in, const int* in_sizes, int n_in,
                              void* d_out, int out_size) {
    const float* x     = (const float*)d_in[0];
    const float* noise = (const float*)d_in[1];
    const float* Wr    = (const float*)d_in[2];
    const float* br    = (const float*)d_in[3];
    const float* W1    = (const float*)d_in[4];
    const float* b1    = (const float*)d_in[5];
    const float* W2    = (const float*)d_in[6];
    const float* b2    = (const float*)d_in[7];
    const float* Ws1   = (const float*)d_in[8];
    const float* bs1   = (const float*)d_in[9];
    const float* Ws2   = (const float*)d_in[10];
    const float* bs2   = (const float*)d_in[11];
    const float* alpha = (const float*)d_in[12];
    const float* beta  = (const float*)d_in[13];

    __half* w1h;  cudaGetSymbolAddress((void**)&w1h,  g_w1h);
    __half* w2h;  cudaGetSymbolAddress((void**)&w2h,  g_w2h);
    __half* ws1h; cudaGetSymbolAddress((void**)&ws1h, g_ws1h);
    __half* ws2h; cudaGetSymbolAddress((void**)&ws2h, g_ws2h);

    const int SMEM = 3 * 10240 + 3 * 8704;   // 56832
    cudaFuncSetAttribute(mma_gemm<1>, cudaFuncAttributeMaxDynamicSharedMemorySize, SMEM);
    cudaFuncSetAttribute(mma_gemm<2>, cudaFuncAttributeMaxDynamicSharedMemorySize, SMEM);

    cudaStream_t stW, stX;
    cudaStreamCreateWithFlags(&stW, cudaStreamNonBlocking);
    cudaStreamCreateWithFlags(&stX, cudaStreamNonBlocking);
    cudaEvent_t evRoot, evW1, evW2, evX;
    cudaEventCreateWithFlags(&evRoot, cudaEventDisableTiming);
    cudaEventCreateWithFlags(&evW1,   cudaEventDisableTiming);
    cudaEventCreateWithFlags(&evW2,   cudaEventDisableTiming);
    cudaEventCreateWithFlags(&evX,    cudaEventDisableTiming);

    const int nW  = NEXP * DIM * HID / 4;
    const int nWs = DIM * HID / 4;
    const int nL  = nW + nWs;

    // fork side streams immediately
    cudaEventRecord(evRoot, 0);
    cudaStreamWaitEvent(stW, evRoot, 0);
    cudaStreamWaitEvent(stX, evRoot, 0);

    // side stream W: layer-1 weights, then layer-2 weights
    conv_w_kernel<<<(nL + 255) / 256, 256, 0, stW>>>(
        (const float4*)W1, (uint2*)w1h, nW, (const float4*)Ws1, (uint2*)ws1h, nWs);
    cudaEventRecord(evW1, stW);
    conv_w_kernel<<<(nL + 255) / 256, 256, 0, stW>>>(
        (const float4*)W2, (uint2*)w2h, nW, (const float4*)Ws2, (uint2*)ws2h, nWs);
    cudaEventRecord(evW2, stW);

    // side stream X: x -> fp16 (parallel with router)
    prep_x_kernel<<<(T_TOK * DIM / 4 + 255) / 256, 256, 0, stX>>>(x);
    cudaEventRecord(evX, stX);

    // main stream: routing (g_cnt zeroed by previous run's combine / load-init)
    router_kernel<<<T_TOK / 4, 128>>>(x, noise, Wr, br);

    // GEMM1: needs router (program order) + prep_x + layer-1 weights
    cudaStreamWaitEvent(0, evX, 0);
    cudaStreamWaitEvent(0, evW1, 0);
    mma_gemm<1><<<dim3(HID / 128, T_TOK / 128, NEXP + 1), 256, SMEM>>>(b1, bs1);
    // GEMM2 (split-K=2): additionally needs layer-2 weights
    cudaStreamWaitEvent(0, evW2, 0);
    mma_gemm<2><<<dim3(2 * DIM / 128, T_TOK / 128, NEXP + 1), 256, SMEM>>>(b2, bs2);
    combine_kernel<<<(T_TOK * DIM / 4 + 255) / 256, 256>>>(alpha, beta, (float4*)d_out);

    cudaEventDestroy(evRoot);
    cudaEventDestroy(evW1);
    cudaEventDestroy(evW2);
    cudaEventDestroy(evX);
    cudaStreamDestroy(stW);
    cudaStreamDestroy(stX);
}

// round 15
// speedup vs baseline: 1.2752x; 1.2752x over previous
#include <cuda_runtime.h>
#include <cuda_fp16.h>
#include <cstdint>

#define T_TOK 2048
#define DIM   768
#define HID   3072
#define NEXP  8

// ---------------- scratch (device globals) ----------------------------------
__device__ int   g_cnt[NEXP];                       // zero at load; reset by combine
__device__ int   g_plist[NEXP * T_TOK];
__device__ float g_pw[2 * T_TOK];
__device__ float g_moe2[(size_t)2 * T_TOK * DIM];   // per-pair L2 output
__device__ float g_sh[T_TOK * DIM];

__device__ __align__(16) __half g_x  [(size_t)T_TOK * DIM];
__device__ __align__(16) __half g_hs [(size_t)T_TOK * HID];
__device__ __align__(16) __half g_h  [(size_t)2 * T_TOK * HID];
__device__ __align__(16) __half g_w1h [(size_t)NEXP * DIM * HID];  // native [K,N]
__device__ __align__(16) __half g_ws1h[(size_t)DIM * HID];
__device__ __align__(16) __half g_w2h [(size_t)NEXP * HID * DIM];
__device__ __align__(16) __half g_ws2h[(size_t)HID * DIM];

// ---------------- helpers ----------------------------------------------------
__device__ __forceinline__ uint32_t smem_u32(const void* p) {
    uint32_t a;
    asm("{ .reg .u64 t; cvta.to.shared.u64 t, %1; cvt.u32.u64 %0, t; }"
        : "=r"(a) : "l"(p));
    return a;
}
#define CP16(saddr, gptr) \
    asm volatile("cp.async.cg.shared.global [%0], [%1], 16;" \
                 :: "r"(saddr), "l"(gptr) : "memory")
#define CP_COMMIT() asm volatile("cp.async.commit_group;" ::: "memory")
template <int N>
__device__ __forceinline__ void cp_wait() {
    asm volatile("cp.async.wait_group %0;" :: "n"(N) : "memory");
}
#define LDM_X4(r, addr) \
    asm volatile("ldmatrix.sync.aligned.m8n8.x4.shared.b16 {%0,%1,%2,%3}, [%4];" \
                 : "=r"((r)[0]), "=r"((r)[1]), "=r"((r)[2]), "=r"((r)[3]) \
                 : "r"(addr))
#define LDM_X4_T(r, addr) \
    asm volatile("ldmatrix.sync.aligned.m8n8.x4.trans.shared.b16 {%0,%1,%2,%3}, [%4];" \
                 : "=r"((r)[0]), "=r"((r)[1]), "=r"((r)[2]), "=r"((r)[3]) \
                 : "r"(addr))
__device__ __forceinline__ void mma16816(float* d, const uint32_t* a,
                                         uint32_t b0, uint32_t b1) {
    asm volatile(
        "mma.sync.aligned.m16n8k16.row.col.f32.f16.f16.f32 "
        "{%0,%1,%2,%3}, {%4,%5,%6,%7}, {%8,%9}, {%0,%1,%2,%3};"
        : "+f"(d[0]), "+f"(d[1]), "+f"(d[2]), "+f"(d[3])
        : "r"(a[0]), "r"(a[1]), "r"(a[2]), "r"(a[3]), "r"(b0), "r"(b1));
}

// ---------------- router: one warp per token --------------------------------
__global__ void router_kernel(const float* __restrict__ x,
                              const float* __restrict__ noise,
                              const float* __restrict__ Wr,
                              const float* __restrict__ br) {
    int warp = (blockIdx.x * blockDim.x + threadIdx.x) >> 5;
    int lane = threadIdx.x & 31;
    if (warp >= T_TOK) return;
    const float* xr = x + warp * DIM;
    float acc[8] = {0.f, 0.f, 0.f, 0.f, 0.f, 0.f, 0.f, 0.f};
    for (int j = lane; j < DIM; j += 32) {
        float xv = xr[j];
        const float4* w4 = reinterpret_cast<const float4*>(Wr + j * NEXP);
        float4 wa = w4[0], wb = w4[1];
        acc[0] += xv * wa.x; acc[1] += xv * wa.y;
        acc[2] += xv * wa.z; acc[3] += xv * wa.w;
        acc[4] += xv * wb.x; acc[5] += xv * wb.y;
        acc[6] += xv * wb.z; acc[7] += xv * wb.w;
    }
#pragma unroll
    for (int off = 16; off; off >>= 1)
#pragma unroll
        for (int e = 0; e < 8; e++)
            acc[e] += __shfl_xor_sync(0xffffffffu, acc[e], off);
    if (lane == 0) {
        float lg[8];
#pragma unroll
        for (int e = 0; e < 8; e++)
            lg[e] = acc[e] + br[e] + 0.1f * noise[warp * NEXP + e];
        int i0 = 0;
#pragma unroll
        for (int e = 1; e < 8; e++) if (lg[e] > lg[i0]) i0 = e;
        int i1 = (i0 == 0) ? 1 : 0;
#pragma unroll
        for (int e = 0; e < 8; e++) if (e != i0 && lg[e] > lg[i1]) i1 = e;
        float e1 = expf(lg[i1] - lg[i0]);
        float w0 = 1.0f / (1.0f + e1);
        g_pw[2 * warp]     = w0;
        g_pw[2 * warp + 1] = e1 * w0;
        int p0 = atomicAdd(&g_cnt[i0], 1);
        g_plist[i0 * T_TOK + p0] = 2 * warp;
        int p1 = atomicAdd(&g_cnt[i1], 1);
        g_plist[i1 * T_TOK + p1] = 2 * warp + 1;
    }
}

// ---------------- prep: x -> fp16 -------------------------------------------
__global__ void prep_x_kernel(const float* __restrict__ x) {
    int i = blockIdx.x * blockDim.x + threadIdx.x;
    const int n4 = T_TOK * DIM / 4;
    if (i >= n4) return;
    float4 v = reinterpret_cast<const float4*>(x)[i];
    __half2 h0 = __floats2half2_rn(v.x, v.y);
    __half2 h1 = __floats2half2_rn(v.z, v.w);
    uint2 pk;
    pk.x = *reinterpret_cast<uint32_t*>(&h0);
    pk.y = *reinterpret_cast<uint32_t*>(&h1);
    reinterpret_cast<uint2*>(g_x)[i] = pk;
}

// ---------------- conv: one layer's weights (expert + shared) ----------------
__global__ void conv_w_kernel(const float4* __restrict__ srcE,
                              uint2* __restrict__ dstE, int nE,
                              const float4* __restrict__ srcS,
                              uint2* __restrict__ dstS, int nS) {
    int i = blockIdx.x * blockDim.x + threadIdx.x;
    const float4* src;
    uint2* dst;
    int j;
    if (i < nE)           { src = srcE; dst = dstE; j = i; }
    else if (i < nE + nS) { src = srcS; dst = dstS; j = i - nE; }
    else return;
    float4 v = src[j];
    __half2 h0 = __floats2half2_rn(v.x, v.y);
    __half2 h1 = __floats2half2_rn(v.z, v.w);
    uint2 pk;
    pk.x = *reinterpret_cast<uint32_t*>(&h0);
    pk.y = *reinterpret_cast<uint32_t*>(&h1);
    dst[j] = pk;
}

// ---------------- HMMA GEMM, 3-stage cp.async ring, occ=2 --------------------
// block 128x128, 8 warps 4(M)x2(N), warp tile 32x64, K-chunk 32.
// A smem: [row][k] 80B pitch; B smem: [k][n] 272B pitch (native [K,N] weights,
// ldmatrix.trans). One __syncthreads per K-chunk.
// grid.z: z<8 => expert z (gathered rows); z==8 => shared expert (dense).
template <int LAYER>
__global__ __launch_bounds__(256, 2)
void mma_gemm(const float* __restrict__ bias_moe,
              const float* __restrict__ bias_sh) {
    constexpr int K = (LAYER == 1) ? DIM : HID;
    constexpr int N = (LAYER == 1) ? HID : DIM;
    constexpr int S = K / 32;
    constexpr int BUFA = 128 * 80;    // 10240
    constexpr int BUFB = 32 * 272;    // 8704

    const int bn = blockIdx.x, bm = blockIdx.y, e = blockIdx.z;
    const bool sh = (e == NEXP);
    const int M = sh ? T_TOK : g_cnt[e];
    if (bm * 128 >= M) return;

    const __half* Bg;
    const float* bp;
    if (LAYER == 1) {
        Bg = sh ? g_ws1h : g_w1h + (size_t)e * DIM * HID;
        bp = (sh ? bias_sh : bias_moe + e * HID) + bn * 128;
    } else {
        Bg = sh ? g_ws2h : g_w2h + (size_t)e * HID * DIM;
        bp = (sh ? bias_sh : bias_moe + e * DIM) + bn * 128;
    }
    Bg += bn * 128;

    extern __shared__ __align__(16) char dsm[];
    char* sm_a = dsm;                 // 3 x BUFA
    char* sm_b = dsm + 3 * BUFA;      // 3 x BUFB
    __shared__ int plist_s[128];

    const int tid = threadIdx.x;
    const int lid = tid & 31, wid = tid >> 5;
    const int wm = wid >> 1, wn = wid & 1;

    if (!sh) {
        if (tid < 128) {
            int r = bm * 128 + tid;
            plist_s[tid] = (r < M) ? g_plist[e * T_TOK + tid + bm * 128] : -1;
        }
        __syncthreads();
    }

    // ---- A cp.async: 2 threads per row, 32B each ----
    const int lrow = tid >> 1;
    const int c4   = (tid & 1) * 2;
    const __half* arow;
    if (sh) {
        arow = ((LAYER == 1) ? g_x : g_hs) + (size_t)(bm * 128 + lrow) * K;
    } else {
        int p  = plist_s[lrow];
        int rr = (p >= 0) ? ((LAYER == 1) ? (p >> 1) : p) : 0;
        arow = ((LAYER == 1) ? g_x : g_h) + (size_t)rr * K;
    }
    arow += c4 * 8;
    const uint32_t sa0 = smem_u32(sm_a) + lrow * 80 + c4 * 16;

    // ---- B cp.async: [k][n] rows, 272B pitch ----
    const int brow_ = tid >> 3;
    const int bseg  = (tid & 7) * 2;
    const __half* bgp = Bg + (size_t)brow_ * N + bseg * 8;
    const uint32_t sb0 = smem_u32(sm_b) + brow_ * 272 + bseg * 16;

    // ---- ldmatrix bases ----
    const uint32_t aBase = smem_u32(sm_a)
        + (wm * 32 + ((lid >> 3) & 1) * 8 + (lid & 7)) * 80
        + (((lid >> 4) & 1) * 8) * 2;
    const int bmx = lid >> 3, brr = lid & 7;
    const uint32_t bBase = smem_u32(sm_b)
        + (brr + (bmx & 1) * 8) * 272
        + (wn * 64 + (bmx >> 1) * 8) * 2;

    float acc[2][8][4];
#pragma unroll
    for (int i = 0; i < 2; i++)
#pragma unroll
        for (int j = 0; j < 8; j++)
#pragma unroll
            for (int k = 0; k < 4; k++) acc[i][j][k] = 0.0f;

    auto load_stage = [&](int st) {
        const __half* ga = arow + st * 32;
        const __half* gb = bgp + (size_t)st * 32 * N;
        const uint32_t da = sa0 + (st % 3) * BUFA;
        const uint32_t db = sb0 + (st % 3) * BUFB;
        CP16(da,      ga);
        CP16(da + 16, ga + 8);
        CP16(db,      gb);
        CP16(db + 16, gb + 8);
    };

    load_stage(0); CP_COMMIT();
    load_stage(1); CP_COMMIT();

    for (int s = 0; s < S; ++s) {
        cp_wait<1>();
        __syncthreads();
        if (s + 2 < S) load_stage(s + 2);
        CP_COMMIT();

        const uint32_t ab = (s % 3) * BUFA;
        const uint32_t bb = (s % 3) * BUFB;
#pragma unroll
        for (int kk = 0; kk < 32; kk += 16) {
            uint32_t af[2][4], bt[4][4];
#pragma unroll
            for (int mi = 0; mi < 2; mi++)
                LDM_X4(af[mi], aBase + ab + mi * 16 * 80 + kk * 2);
#pragma unroll
            for (int g = 0; g < 4; g++)
                LDM_X4_T(bt[g], bBase + bb + kk * 272 + g * 32);
#pragma unroll
            for (int mi = 0; mi < 2; mi++)
#pragma unroll
                for (int g = 0; g < 4; g++) {
                    mma16816(acc[mi][2 * g],     af[mi], bt[g][0], bt[g][1]);
                    mma16816(acc[mi][2 * g + 1], af[mi], bt[g][2], bt[g][3]);
                }
        }
    }

    // ---- epilogue ----
    const int lr = lid >> 2;
    const int lc = (lid & 3) * 2;
#pragma unroll
    for (int mi = 0; mi < 2; mi++) {
#pragma unroll
        for (int h = 0; h < 2; h++) {
            int rl = wm * 32 + mi * 16 + h * 8 + lr;
            int r  = bm * 128 + rl;
            int p = 0;
            float gw = 0.f;
            if (!sh) {
                p = plist_s[rl];
                if (p < 0) continue;
                gw = g_pw[p];
            }
            if (LAYER == 1) {
                __half* dh = sh ? (g_hs + (size_t)r * HID)
                                : (g_h  + (size_t)p * HID);
#pragma unroll
                for (int nj = 0; nj < 8; nj++) {
                    int cl = wn * 64 + nj * 8 + lc;
                    float v0 = acc[mi][nj][2 * h]     + bp[cl];
                    float v1 = acc[mi][nj][2 * h + 1] + bp[cl + 1];
                    v0 = (v0 > 0.f) ? v0 : 0.01f * v0;
                    v1 = (v1 > 0.f) ? v1 : 0.01f * v1;
                    *reinterpret_cast<__half2*>(dh + bn * 128 + cl) =
                        __floats2half2_rn(v0, v1);
                }
            } else if (sh) {
                float* d = g_sh + (size_t)r * DIM;
#pragma unroll
                for (int nj = 0; nj < 8; nj++) {
                    int cl = wn * 64 + nj * 8 + lc;
                    float2 v;
                    v.x = acc[mi][nj][2 * h]     + bp[cl];
                    v.y = acc[mi][nj][2 * h + 1] + bp[cl + 1];
                    *reinterpret_cast<float2*>(d + bn * 128 + cl) = v;
                }
            } else {
                float* d = g_moe2 + (size_t)p * DIM;
#pragma unroll
                for (int nj = 0; nj < 8; nj++) {
                    int cl = wn * 64 + nj * 8 + lc;
                    float2 v;
                    v.x = gw * (acc[mi][nj][2 * h]     + bp[cl]);
                    v.y = gw * (acc[mi][nj][2 * h + 1] + bp[cl + 1]);
                    *reinterpret_cast<float2*>(d + bn * 128 + cl) = v;
                }
            }
        }
    }
}

// ---------------- final mix (float4) + counter reset --------------------------
__global__ void combine_kernel(const float* __restrict__ alpha,
                               const float* __restrict__ beta,
                               float4* __restrict__ out) {
    // reset expert counters for the next replay (all GEMMs already done)
    if (blockIdx.x == 0 && threadIdx.x < NEXP) g_cnt[threadIdx.x] = 0;

    float a = *alpha, b = *beta;
    float m  = fmaxf(a, b);
    float ea = expf(a - m), eb = expf(b - m);
    float inv = 1.0f / (ea + eb);
    float w0 = ea * inv, w1 = eb * inv;
    const int D4 = DIM / 4;
    const int n4 = T_TOK * D4;
    int i = blockIdx.x * blockDim.x + threadIdx.x;
    if (i >= n4) return;
    int t = i / D4, j = i - t * D4;
    const float4* m4 = reinterpret_cast<const float4*>(g_moe2);
    float4 m0 = m4[(size_t)(2 * t) * D4 + j];
    float4 m1 = m4[(size_t)(2 * t + 1) * D4 + j];
    float4 sv = reinterpret_cast<const float4*>(g_sh)[i];
    float4 o;
    o.x = w0 * sv.x + w1 * (m0.x + m1.x);
    o.y = w0 * sv.y + w1 * (m0.y + m1.y);
    o.z = w0 * sv.z + w1 * (m0.z + m1.z);
    o.w = w0 * sv.w + w1 * (m0.w + m1.w);
    out[i] = o;
}

// ---------------- launch ----------------------------------------------------
extern "C" void kernel_launch(void* const* d_in, const int* in_sizes, int n_in,
                              void* d_out, int out_size) {
    const float* x     = (const float*)d_in[0];
    const float* noise = (const float*)d_in[1];
    const float* Wr    = (const float*)d_in[2];
    const float* br    = (const float*)d_in[3];
    const float* W1    = (const float*)d_in[4];
    const float* b1    = (const float*)d_in[5];
    const float* W2    = (const float*)d_in[6];
    const float* b2    = (const float*)d_in[7];
    const float* Ws1   = (const float*)d_in[8];
    const float* bs1   = (const float*)d_in[9];
    const float* Ws2   = (const float*)d_in[10];
    const float* bs2   = (const float*)d_in[11];
    const float* alpha = (const float*)d_in[12];
    const float* beta  = (const float*)d_in[13];

    __half* w1h;  cudaGetSymbolAddress((void**)&w1h,  g_w1h);
    __half* w2h;  cudaGetSymbolAddress((void**)&w2h,  g_w2h);
    __half* ws1h; cudaGetSymbolAddress((void**)&ws1h, g_ws1h);
    __half* ws2h; cudaGetSymbolAddress((void**)&ws2h, g_ws2h);

    const int SMEM = 3 * 10240 + 3 * 8704;   // 56832
    cudaFuncSetAttribute(mma_gemm<1>, cudaFuncAttributeMaxDynamicSharedMemorySize, SMEM);
    cudaFuncSetAttribute(mma_gemm<2>, cudaFuncAttributeMaxDynamicSharedMemorySize, SMEM);

    cudaStream_t stW, stX;
    cudaStreamCreateWithFlags(&stW, cudaStreamNonBlocking);
    cudaStreamCreateWithFlags(&stX, cudaStreamNonBlocking);
    cudaEvent_t evRoot, evW1, evW2, evX;
    cudaEventCreateWithFlags(&evRoot, cudaEventDisableTiming);
    cudaEventCreateWithFlags(&evW1,   cudaEventDisableTiming);
    cudaEventCreateWithFlags(&evW2,   cudaEventDisableTiming);
    cudaEventCreateWithFlags(&evX,    cudaEventDisableTiming);

    const int nW  = NEXP * DIM * HID / 4;
    const int nWs = DIM * HID / 4;
    const int nL  = nW + nWs;

    // fork side streams immediately
    cudaEventRecord(evRoot, 0);
    cudaStreamWaitEvent(stW, evRoot, 0);
    cudaStreamWaitEvent(stX, evRoot, 0);

    // side stream W: layer-1 weights, then layer-2 weights
    conv_w_kernel<<<(nL + 255) / 256, 256, 0, stW>>>(
        (const float4*)W1, (uint2*)w1h, nW, (const float4*)Ws1, (uint2*)ws1h, nWs);
    cudaEventRecord(evW1, stW);
    conv_w_kernel<<<(nL + 255) / 256, 256, 0, stW>>>(
        (const float4*)W2, (uint2*)w2h, nW, (const float4*)Ws2, (uint2*)ws2h, nWs);
    cudaEventRecord(evW2, stW);

    // side stream X: x -> fp16 (parallel with router)
    prep_x_kernel<<<(T_TOK * DIM / 4 + 255) / 256, 256, 0, stX>>>(x);
    cudaEventRecord(evX, stX);

    // main stream: routing (g_cnt zero at load / reset by previous combine)
    router_kernel<<<T_TOK / 4, 128>>>(x, noise, Wr, br);

    // GEMM1: needs router (program order) + prep_x + layer-1 weights
    cudaStreamWaitEvent(0, evX, 0);
    cudaStreamWaitEvent(0, evW1, 0);
    mma_gemm<1><<<dim3(HID / 128, T_TOK / 128, NEXP + 1), 256, SMEM>>>(b1, bs1);
    // GEMM2: additionally needs layer-2 weights (converted under GEMM1)
    cudaStreamWaitEvent(0, evW2, 0);
    mma_gemm<2><<<dim3(DIM / 128, T_TOK / 128, NEXP + 1), 256, SMEM>>>(b2, bs2);
    combine_kernel<<<(T_TOK * DIM / 4 + 255) / 256, 256>>>(alpha, beta, (float4*)d_out);

    cudaEventDestroy(evRoot);
    cudaEventDestroy(evW1);
    cudaEventDestroy(evW2);
    cudaEventDestroy(evX);
    cudaStreamDestroy(stW);
    cudaStreamDestroy(stX);
}

// round 16
// speedup vs baseline: 1.2753x; 1.0001x over previous
#include <cuda_runtime.h>
#include <cuda_fp16.h>
#include <cstdint>

#define T_TOK 2048
#define DIM   768
#define HID   3072
#define NEXP  8

// ---------------- scratch (device globals) ----------------------------------
__device__ int   g_cnt[NEXP];
__device__ int   g_plist[NEXP * T_TOK];
__device__ float g_pw[2 * T_TOK];
__device__ float g_moe2[(size_t)2 * T_TOK * DIM];   // per-pair L2 output
__device__ float g_sh[T_TOK * DIM];

__device__ __align__(16) __half g_x  [(size_t)T_TOK * DIM];
__device__ __align__(16) __half g_hs [(size_t)T_TOK * HID];
__device__ __align__(16) __half g_h  [(size_t)2 * T_TOK * HID];
__device__ __align__(16) __half g_w1h [(size_t)NEXP * DIM * HID];  // native [K,N]
__device__ __align__(16) __half g_ws1h[(size_t)DIM * HID];
__device__ __align__(16) __half g_w2h [(size_t)NEXP * HID * DIM];
__device__ __align__(16) __half g_ws2h[(size_t)HID * DIM];

// ---------------- helpers ----------------------------------------------------
__device__ __forceinline__ uint32_t smem_u32(const void* p) {
    uint32_t a;
    asm("{ .reg .u64 t; cvta.to.shared.u64 t, %1; cvt.u32.u64 %0, t; }"
        : "=r"(a) : "l"(p));
    return a;
}
#define CP16(saddr, gptr) \
    asm volatile("cp.async.cg.shared.global [%0], [%1], 16;" \
                 :: "r"(saddr), "l"(gptr) : "memory")
#define CP_COMMIT() asm volatile("cp.async.commit_group;" ::: "memory")
template <int N>
__device__ __forceinline__ void cp_wait() {
    asm volatile("cp.async.wait_group %0;" :: "n"(N) : "memory");
}
#define LDM_X4(r, addr) \
    asm volatile("ldmatrix.sync.aligned.m8n8.x4.shared.b16 {%0,%1,%2,%3}, [%4];" \
                 : "=r"((r)[0]), "=r"((r)[1]), "=r"((r)[2]), "=r"((r)[3]) \
                 : "r"(addr))
#define LDM_X4_T(r, addr) \
    asm volatile("ldmatrix.sync.aligned.m8n8.x4.trans.shared.b16 {%0,%1,%2,%3}, [%4];" \
                 : "=r"((r)[0]), "=r"((r)[1]), "=r"((r)[2]), "=r"((r)[3]) \
                 : "r"(addr))
__device__ __forceinline__ void mma16816(float* d, const uint32_t* a,
                                         uint32_t b0, uint32_t b1) {
    asm volatile(
        "mma.sync.aligned.m16n8k16.row.col.f32.f16.f16.f32 "
        "{%0,%1,%2,%3}, {%4,%5,%6,%7}, {%8,%9}, {%0,%1,%2,%3};"
        : "+f"(d[0]), "+f"(d[1]), "+f"(d[2]), "+f"(d[3])
        : "r"(a[0]), "r"(a[1]), "r"(a[2]), "r"(a[3]), "r"(b0), "r"(b1));
}

// ---------------- zero counters ----------------------------------------------
__global__ void zero_kernel() {
    if (threadIdx.x < NEXP) g_cnt[threadIdx.x] = 0;
}

// ---------------- router: one warp per token --------------------------------
__global__ void router_kernel(const float* __restrict__ x,
                              const float* __restrict__ noise,
                              const float* __restrict__ Wr,
                              const float* __restrict__ br) {
    int warp = (blockIdx.x * blockDim.x + threadIdx.x) >> 5;
    int lane = threadIdx.x & 31;
    if (warp >= T_TOK) return;
    const float* xr = x + warp * DIM;
    float acc[8] = {0.f, 0.f, 0.f, 0.f, 0.f, 0.f, 0.f, 0.f};
    for (int j = lane; j < DIM; j += 32) {
        float xv = xr[j];
        const float4* w4 = reinterpret_cast<const float4*>(Wr + j * NEXP);
        float4 wa = w4[0], wb = w4[1];
        acc[0] += xv * wa.x; acc[1] += xv * wa.y;
        acc[2] += xv * wa.z; acc[3] += xv * wa.w;
        acc[4] += xv * wb.x; acc[5] += xv * wb.y;
        acc[6] += xv * wb.z; acc[7] += xv * wb.w;
    }
#pragma unroll
    for (int off = 16; off; off >>= 1)
#pragma unroll
        for (int e = 0; e < 8; e++)
            acc[e] += __shfl_xor_sync(0xffffffffu, acc[e], off);
    if (lane == 0) {
        float lg[8];
#pragma unroll
        for (int e = 0; e < 8; e++)
            lg[e] = acc[e] + br[e] + 0.1f * noise[warp * NEXP + e];
        int i0 = 0;
#pragma unroll
        for (int e = 1; e < 8; e++) if (lg[e] > lg[i0]) i0 = e;
        int i1 = (i0 == 0) ? 1 : 0;
#pragma unroll
        for (int e = 0; e < 8; e++) if (e != i0 && lg[e] > lg[i1]) i1 = e;
        float e1 = expf(lg[i1] - lg[i0]);
        float w0 = 1.0f / (1.0f + e1);
        g_pw[2 * warp]     = w0;
        g_pw[2 * warp + 1] = e1 * w0;
        int p0 = atomicAdd(&g_cnt[i0], 1);
        g_plist[i0 * T_TOK + p0] = 2 * warp;
        int p1 = atomicAdd(&g_cnt[i1], 1);
        g_plist[i1 * T_TOK + p1] = 2 * warp + 1;
    }
}

// ---------------- prep: x -> fp16 -------------------------------------------
__global__ void prep_x_kernel(const float* __restrict__ x) {
    int i = blockIdx.x * blockDim.x + threadIdx.x;
    const int n4 = T_TOK * DIM / 4;
    if (i >= n4) return;
    float4 v = reinterpret_cast<const float4*>(x)[i];
    __half2 h0 = __floats2half2_rn(v.x, v.y);
    __half2 h1 = __floats2half2_rn(v.z, v.w);
    uint2 pk;
    pk.x = *reinterpret_cast<uint32_t*>(&h0);
    pk.y = *reinterpret_cast<uint32_t*>(&h1);
    reinterpret_cast<uint2*>(g_x)[i] = pk;
}

// ---------------- conv: one layer's weights (expert + shared) ----------------
__global__ void conv_w_kernel(const float4* __restrict__ srcE,
                              uint2* __restrict__ dstE, int nE,
                              const float4* __restrict__ srcS,
                              uint2* __restrict__ dstS, int nS) {
    int i = blockIdx.x * blockDim.x + threadIdx.x;
    const float4* src;
    uint2* dst;
    int j;
    if (i < nE)           { src = srcE; dst = dstE; j = i; }
    else if (i < nE + nS) { src = srcS; dst = dstS; j = i - nE; }
    else return;
    float4 v = src[j];
    __half2 h0 = __floats2half2_rn(v.x, v.y);
    __half2 h1 = __floats2half2_rn(v.z, v.w);
    uint2 pk;
    pk.x = *reinterpret_cast<uint32_t*>(&h0);
    pk.y = *reinterpret_cast<uint32_t*>(&h1);
    dst[j] = pk;
}

// ---------------- HMMA GEMM, 3-stage cp.async ring, occ=2 --------------------
// block 128x128, 8 warps 4(M)x2(N), warp tile 32x64, K-chunk 32.
// A smem: [row][k] 80B pitch; B smem: [k][n] 272B pitch (native [K,N] weights,
// ldmatrix.trans). One __syncthreads per K-chunk.
// effective expert id e = blockIdx.z + ZOFF; e<8 => expert (gathered rows);
// e==8 => shared expert (dense). ZOFF lets us launch the shared slice alone
// (grid.z=1, ZOFF=8) concurrently with the router.
template <int LAYER, int ZOFF>
__global__ __launch_bounds__(256, 2)
void mma_gemm(const float* __restrict__ bias_moe,
              const float* __restrict__ bias_sh) {
    constexpr int K = (LAYER == 1) ? DIM : HID;
    constexpr int N = (LAYER == 1) ? HID : DIM;
    constexpr int S = K / 32;
    constexpr int BUFA = 128 * 80;    // 10240
    constexpr int BUFB = 32 * 272;    // 8704

    const int bn = blockIdx.x, bm = blockIdx.y;
    const int e = blockIdx.z + ZOFF;
    const bool sh = (e == NEXP);
    const int M = sh ? T_TOK : g_cnt[e];
    if (bm * 128 >= M) return;

    const __half* Bg;
    const float* bp;
    if (LAYER == 1) {
        Bg = sh ? g_ws1h : g_w1h + (size_t)e * DIM * HID;
        bp = (sh ? bias_sh : bias_moe + e * HID) + bn * 128;
    } else {
        Bg = sh ? g_ws2h : g_w2h + (size_t)e * HID * DIM;
        bp = (sh ? bias_sh : bias_moe + e * DIM) + bn * 128;
    }
    Bg += bn * 128;

    extern __shared__ __align__(16) char dsm[];
    char* sm_a = dsm;                 // 3 x BUFA
    char* sm_b = dsm + 3 * BUFA;      // 3 x BUFB
    __shared__ int plist_s[128];

    const int tid = threadIdx.x;
    const int lid = tid & 31, wid = tid >> 5;
    const int wm = wid >> 1, wn = wid & 1;

    if (!sh) {
        if (tid < 128) {
            int r = bm * 128 + tid;
            plist_s[tid] = (r < M) ? g_plist[e * T_TOK + tid + bm * 128] : -1;
        }
        __syncthreads();
    }

    // ---- A cp.async: 2 threads per row, 32B each ----
    const int lrow = tid >> 1;
    const int c4   = (tid & 1) * 2;
    const __half* arow;
    if (sh) {
        arow = ((LAYER == 1) ? g_x : g_hs) + (size_t)(bm * 128 + lrow) * K;
    } else {
        int p  = plist_s[lrow];
        int rr = (p >= 0) ? ((LAYER == 1) ? (p >> 1) : p) : 0;
        arow = ((LAYER == 1) ? g_x : g_h) + (size_t)rr * K;
    }
    arow += c4 * 8;
    const uint32_t sa0 = smem_u32(sm_a) + lrow * 80 + c4 * 16;

    // ---- B cp.async: [k][n] rows, 272B pitch ----
    const int brow_ = tid >> 3;
    const int bseg  = (tid & 7) * 2;
    const __half* bgp = Bg + (size_t)brow_ * N + bseg * 8;
    const uint32_t sb0 = smem_u32(sm_b) + brow_ * 272 + bseg * 16;

    // ---- ldmatrix bases ----
    const uint32_t aBase = smem_u32(sm_a)
        + (wm * 32 + ((lid >> 3) & 1) * 8 + (lid & 7)) * 80
        + (((lid >> 4) & 1) * 8) * 2;
    const int bmx = lid >> 3, brr = lid & 7;
    const uint32_t bBase = smem_u32(sm_b)
        + (brr + (bmx & 1) * 8) * 272
        + (wn * 64 + (bmx >> 1) * 8) * 2;

    float acc[2][8][4];
#pragma unroll
    for (int i = 0; i < 2; i++)
#pragma unroll
        for (int j = 0; j < 8; j++)
#pragma unroll
            for (int k = 0; k < 4; k++) acc[i][j][k] = 0.0f;

    auto load_stage = [&](int st) {
        const __half* ga = arow + st * 32;
        const __half* gb = bgp + (size_t)st * 32 * N;
        const uint32_t da = sa0 + (st % 3) * BUFA;
        const uint32_t db = sb0 + (st % 3) * BUFB;
        CP16(da,      ga);
        CP16(da + 16, ga + 8);
        CP16(db,      gb);
        CP16(db + 16, gb + 8);
    };

    load_stage(0); CP_COMMIT();
    load_stage(1); CP_COMMIT();

    for (int s = 0; s < S; ++s) {
        cp_wait<1>();
        __syncthreads();
        if (s + 2 < S) load_stage(s + 2);
        CP_COMMIT();

        const uint32_t ab = (s % 3) * BUFA;
        const uint32_t bb = (s % 3) * BUFB;
#pragma unroll
        for (int kk = 0; kk < 32; kk += 16) {
            uint32_t af[2][4], bt[4][4];
#pragma unroll
            for (int mi = 0; mi < 2; mi++)
                LDM_X4(af[mi], aBase + ab + mi * 16 * 80 + kk * 2);
#pragma unroll
            for (int g = 0; g < 4; g++)
                LDM_X4_T(bt[g], bBase + bb + kk * 272 + g * 32);
#pragma unroll
            for (int mi = 0; mi < 2; mi++)
#pragma unroll
                for (int g = 0; g < 4; g++) {
                    mma16816(acc[mi][2 * g],     af[mi], bt[g][0], bt[g][1]);
                    mma16816(acc[mi][2 * g + 1], af[mi], bt[g][2], bt[g][3]);
                }
        }
    }

    // ---- epilogue ----
    const int lr = lid >> 2;
    const int lc = (lid & 3) * 2;
#pragma unroll
    for (int mi = 0; mi < 2; mi++) {
#pragma unroll
        for (int h = 0; h < 2; h++) {
            int rl = wm * 32 + mi * 16 + h * 8 + lr;
            int r  = bm * 128 + rl;
            int p = 0;
            float gw = 0.f;
            if (!sh) {
                p = plist_s[rl];
                if (p < 0) continue;
                gw = g_pw[p];
            }
            if (LAYER == 1) {
                __half* dh = sh ? (g_hs + (size_t)r * HID)
                                : (g_h  + (size_t)p * HID);
#pragma unroll
                for (int nj = 0; nj < 8; nj++) {
                    int cl = wn * 64 + nj * 8 + lc;
                    float v0 = acc[mi][nj][2 * h]     + bp[cl];
                    float v1 = acc[mi][nj][2 * h + 1] + bp[cl + 1];
                    v0 = (v0 > 0.f) ? v0 : 0.01f * v0;
                    v1 = (v1 > 0.f) ? v1 : 0.01f * v1;
                    *reinterpret_cast<__half2*>(dh + bn * 128 + cl) =
                        __floats2half2_rn(v0, v1);
                }
            } else if (sh) {
                float* d = g_sh + (size_t)r * DIM;
#pragma unroll
                for (int nj = 0; nj < 8; nj++) {
                    int cl = wn * 64 + nj * 8 + lc;
                    float2 v;
                    v.x = acc[mi][nj][2 * h]     + bp[cl];
                    v.y = acc[mi][nj][2 * h + 1] + bp[cl + 1];
                    *reinterpret_cast<float2*>(d + bn * 128 + cl) = v;
                }
            } else {
                float* d = g_moe2 + (size_t)p * DIM;
#pragma unroll
                for (int nj = 0; nj < 8; nj++) {
                    int cl = wn * 64 + nj * 8 + lc;
                    float2 v;
                    v.x = gw * (acc[mi][nj][2 * h]     + bp[cl]);
                    v.y = gw * (acc[mi][nj][2 * h + 1] + bp[cl + 1]);
                    *reinterpret_cast<float2*>(d + bn * 128 + cl) = v;
                }
            }
        }
    }
}

// ---------------- final mix (float4) -----------------------------------------
__global__ void combine_kernel(const float* __restrict__ alpha,
                               const float* __restrict__ beta,
                               float4* __restrict__ out) {
    float a = *alpha, b = *beta;
    float m  = fmaxf(a, b);
    float ea = expf(a - m), eb = expf(b - m);
    float inv = 1.0f / (ea + eb);
    float w0 = ea * inv, w1 = eb * inv;
    const int D4 = DIM / 4;
    const int n4 = T_TOK * D4;
    int i = blockIdx.x * blockDim.x + threadIdx.x;
    if (i >= n4) return;
    int t = i / D4, j = i - t * D4;
    const float4* m4 = reinterpret_cast<const float4*>(g_moe2);
    float4 m0 = m4[(size_t)(2 * t) * D4 + j];
    float4 m1 = m4[(size_t)(2 * t + 1) * D4 + j];
    float4 sv = reinterpret_cast<const float4*>(g_sh)[i];
    float4 o;
    o.x = w0 * sv.x + w1 * (m0.x + m1.x);
    o.y = w0 * sv.y + w1 * (m0.y + m1.y);
    o.z = w0 * sv.z + w1 * (m0.z + m1.z);
    o.w = w0 * sv.w + w1 * (m0.w + m1.w);
    out[i] = o;
}

// ---------------- launch ----------------------------------------------------
extern "C" void kernel_launch(void* const* d_in, const int* in_sizes, int n_in,
                              void* d_out, int out_size) {
    const float* x     = (const float*)d_in[0];
    const float* noise = (const float*)d_in[1];
    const float* Wr    = (const float*)d_in[2];
    const float* br    = (const float*)d_in[3];
    const float* W1    = (const float*)d_in[4];
    const float* b1    = (const float*)d_in[5];
    const float* W2    = (const float*)d_in[6];
    const float* b2    = (const float*)d_in[7];
    const float* Ws1   = (const float*)d_in[8];
    const float* bs1   = (const float*)d_in[9];
    const float* Ws2   = (const float*)d_in[10];
    const float* bs2   = (const float*)d_in[11];
    const float* alpha = (const float*)d_in[12];
    const float* beta  = (const float*)d_in[13];

    __half* w1h;  cudaGetSymbolAddress((void**)&w1h,  g_w1h);
    __half* w2h;  cudaGetSymbolAddress((void**)&w2h,  g_w2h);
    __half* ws1h; cudaGetSymbolAddress((void**)&ws1h, g_ws1h);
    __half* ws2h; cudaGetSymbolAddress((void**)&ws2h, g_ws2h);

    const int SMEM = 3 * 10240 + 3 * 8704;   // 56832
    cudaFuncSetAttribute(mma_gemm<1, 0>, cudaFuncAttributeMaxDynamicSharedMemorySize, SMEM);
    cudaFuncSetAttribute(mma_gemm<1, 8>, cudaFuncAttributeMaxDynamicSharedMemorySize, SMEM);
    cudaFuncSetAttribute(mma_gemm<2, 0>, cudaFuncAttributeMaxDynamicSharedMemorySize, SMEM);

    cudaStream_t stW, stX;
    cudaStreamCreateWithFlags(&stW, cudaStreamNonBlocking);
    cudaStreamCreateWithFlags(&stX, cudaStreamNonBlocking);
    cudaEvent_t evRoot, evW1, evW2, evX, evS1;
    cudaEventCreateWithFlags(&evRoot, cudaEventDisableTiming);
    cudaEventCreateWithFlags(&evW1,   cudaEventDisableTiming);
    cudaEventCreateWithFlags(&evW2,   cudaEventDisableTiming);
    cudaEventCreateWithFlags(&evX,    cudaEventDisableTiming);
    cudaEventCreateWithFlags(&evS1,   cudaEventDisableTiming);

    const int nW  = NEXP * DIM * HID / 4;
    const int nWs = DIM * HID / 4;
    const int nL  = nW + nWs;

    // fork side streams immediately
    cudaEventRecord(evRoot, 0);
    cudaStreamWaitEvent(stW, evRoot, 0);
    cudaStreamWaitEvent(stX, evRoot, 0);

    // side stream W: layer-1 weights, then layer-2 weights
    conv_w_kernel<<<(nL + 255) / 256, 256, 0, stW>>>(
        (const float4*)W1, (uint2*)w1h, nW, (const float4*)Ws1, (uint2*)ws1h, nWs);
    cudaEventRecord(evW1, stW);
    conv_w_kernel<<<(nL + 255) / 256, 256, 0, stW>>>(
        (const float4*)W2, (uint2*)w2h, nW, (const float4*)Ws2, (uint2*)ws2h, nWs);
    cudaEventRecord(evW2, stW);

    // side stream X: prep_x, then shared-expert GEMM1 (router-independent);
    // this runs concurrently with the router on the main stream.
    prep_x_kernel<<<(T_TOK * DIM / 4 + 255) / 256, 256, 0, stX>>>(x);
    cudaEventRecord(evX, stX);
    cudaStreamWaitEvent(stX, evW1, 0);
    mma_gemm<1, 8><<<dim3(HID / 128, T_TOK / 128, 1), 256, SMEM, stX>>>(b1, bs1);
    cudaEventRecord(evS1, stX);

    // main stream: routing
    zero_kernel<<<1, 32>>>();
    router_kernel<<<T_TOK / 4, 128>>>(x, noise, Wr, br);

    // GEMM1 moe slice: needs router (in-stream) + prep_x + layer-1 weights
    cudaStreamWaitEvent(0, evX, 0);
    cudaStreamWaitEvent(0, evW1, 0);
    mma_gemm<1, 0><<<dim3(HID / 128, T_TOK / 128, NEXP), 256, SMEM>>>(b1, bs1);
    // GEMM2: needs g_hs (shared GEMM1, evS1) + layer-2 weights (evW2)
    cudaStreamWaitEvent(0, evS1, 0);
    cudaStreamWaitEvent(0, evW2, 0);
    mma_gemm<2, 0><<<dim3(DIM / 128, T_TOK / 128, NEXP + 1), 256, SMEM>>>(b2, bs2);
    combine_kernel<<<(T_TOK * DIM / 4 + 255) / 256, 256>>>(alpha, beta, (float4*)d_out);

    cudaEventDestroy(evRoot);
    cudaEventDestroy(evW1);
    cudaEventDestroy(evW2);
    cudaEventDestroy(evX);
    cudaEventDestroy(evS1);
    cudaStreamDestroy(stW);
    cudaStreamDestroy(stX);
}